// round 1
// baseline (speedup 1.0000x reference)
#include <cuda_runtime.h>
#include <cuda_fp16.h>
#include <cstdint>

#define Bb 32
#define Ss 512
#define Dd 1024
#define Hh 1024
#define Mm (Bb*Ss)     // 16384
#define Nn 4096        // 4 gates * H, interleaved n = 4*h + g  (g: 0=f,1=i,2=l,3=u)
#define Kk 1024

// ---- scratch (device globals; no allocation allowed) ----
__device__ __half g_A[(size_t)Mm*Kk];    // fp16 inp, row-major [m][k]
__device__ __half g_W[(size_t)Kk*Nn];    // fp16 packed weights [k][4h+g]
__device__ float  g_G[(size_t)Mm*Nn];    // gate pre-activations
__device__ float  g_hv[Bb*Nn];           // h0@V_g + B_g, interleaved [b][4h+g]

// ================= convert / pack =================
__global__ void conv_inp_kernel(const float* __restrict__ inp){
    size_t i = (size_t)blockIdx.x*blockDim.x + threadIdx.x;   // float4 index
    float4 v = ((const float4*)inp)[i];
    __half2* dst = (__half2*)g_A + i*2;
    dst[0] = __floats2half2_rn(v.x, v.y);
    dst[1] = __floats2half2_rn(v.z, v.w);
}

__global__ void pack_w_kernel(const float* __restrict__ Uf, const float* __restrict__ Ui,
                              const float* __restrict__ Ul, const float* __restrict__ Uu){
    int idx = blockIdx.x*blockDim.x + threadIdx.x;  // k*1024 + h
    int k = idx >> 10, h = idx & 1023;
    __half2 p0 = __floats2half2_rn(Uf[idx], Ui[idx]);
    __half2 p1 = __floats2half2_rn(Ul[idx], Uu[idx]);
    __half2* dst = (__half2*)(g_W + (size_t)k*Nn + 4*h);
    dst[0] = p0; dst[1] = p1;
}

// ================= hv[b][4h+g] = B_g[h] + sum_k h0[b,k] V_g[k,h] =================
__global__ void hv_kernel(const float* __restrict__ h0,
                          const float* __restrict__ Vf, const float* __restrict__ Vi,
                          const float* __restrict__ Vl, const float* __restrict__ Vu,
                          const float* __restrict__ Bf, const float* __restrict__ Bi,
                          const float* __restrict__ Bl, const float* __restrict__ Bu){
    int b = blockIdx.x >> 2, g = blockIdx.x & 3;
    const float* V  = (g==0)?Vf:(g==1)?Vi:(g==2)?Vl:Vu;
    const float* Bv = (g==0)?Bf:(g==1)?Bi:(g==2)?Bl:Bu;
    __shared__ float sh0[1024];
    for (int k = threadIdx.x; k < 1024; k += 256) sh0[k] = h0[b*1024 + k];
    __syncthreads();
    int t = threadIdx.x;                  // covers h = 4t .. 4t+3
    float4 acc = ((const float4*)Bv)[t];
    #pragma unroll 4
    for (int k = 0; k < 1024; ++k){
        float s = sh0[k];
        float4 v = ((const float4*)(V + (size_t)k*1024))[t];
        acc.x = fmaf(s, v.x, acc.x);
        acc.y = fmaf(s, v.y, acc.y);
        acc.z = fmaf(s, v.z, acc.z);
        acc.w = fmaf(s, v.w, acc.w);
    }
    int h = t*4;
    float* o = g_hv + b*Nn + g;
    o[4*(h+0)] = acc.x; o[4*(h+1)] = acc.y; o[4*(h+2)] = acc.z; o[4*(h+3)] = acc.w;
}

// ================= GEMM: G = A(fp16) * W(fp16) + hv =================
#define BM 128
#define BN 128
#define BKk 32
#define APAD 40     // halfs per A row (pad for conflict-free ldmatrix)
#define BPAD 136    // halfs per B row
#define STAGE_A (BM*APAD*2)    // bytes
#define STAGE_B (BKk*BPAD*2)

__device__ __forceinline__ void cp16(uint32_t d, const void* s){
    asm volatile("cp.async.cg.shared.global [%0], [%1], 16;" :: "r"(d), "l"(s));
}
__device__ __forceinline__ void ldsm_x4(uint32_t& r0,uint32_t& r1,uint32_t& r2,uint32_t& r3,uint32_t a){
    asm volatile("ldmatrix.sync.aligned.m8n8.x4.shared.b16 {%0,%1,%2,%3},[%4];"
        : "=r"(r0),"=r"(r1),"=r"(r2),"=r"(r3) : "r"(a));
}
__device__ __forceinline__ void ldsm_x4t(uint32_t& r0,uint32_t& r1,uint32_t& r2,uint32_t& r3,uint32_t a){
    asm volatile("ldmatrix.sync.aligned.m8n8.x4.trans.shared.b16 {%0,%1,%2,%3},[%4];"
        : "=r"(r0),"=r"(r1),"=r"(r2),"=r"(r3) : "r"(a));
}
__device__ __forceinline__ void mma16816(float* c, const uint32_t* a, const uint32_t* b){
    asm volatile("mma.sync.aligned.m16n8k16.row.col.f32.f16.f16.f32 "
        "{%0,%1,%2,%3},{%4,%5,%6,%7},{%8,%9},{%0,%1,%2,%3};"
        : "+f"(c[0]),"+f"(c[1]),"+f"(c[2]),"+f"(c[3])
        : "r"(a[0]),"r"(a[1]),"r"(a[2]),"r"(a[3]),"r"(b[0]),"r"(b[1]));
}

__global__ __launch_bounds__(256,2) void gemm_kernel(){
    __shared__ __align__(16) __half As[2][BM][APAD];
    __shared__ __align__(16) __half Bs[2][BKk][BPAD];
    const int tid = threadIdx.x;
    const int lane = tid & 31, warp = tid >> 5;
    const int wm = warp >> 2, wn = warp & 3;          // warps 2(m) x 4(n); warp tile 64x32
    const int m0 = blockIdx.y * BM, n0 = blockIdx.x * BN;

    float acc[4][4][4];
    #pragma unroll
    for (int i=0;i<4;i++)
        #pragma unroll
        for (int j=0;j<4;j++){ acc[i][j][0]=0.f; acc[i][j][1]=0.f; acc[i][j][2]=0.f; acc[i][j][3]=0.f; }

    const __half* Ag = g_A + (size_t)m0*Kk;
    const __half* Wg = g_W + n0;
    uint32_t sA = (uint32_t)__cvta_generic_to_shared(&As[0][0][0]);
    uint32_t sB = (uint32_t)__cvta_generic_to_shared(&Bs[0][0][0]);

    const int ar = tid >> 2, ac = (tid & 3)*8;        // A: 128 rows x 32 cols, 16B chunks
    const int bk = tid >> 4, bn = (tid & 15)*8;       // B: 32 rows x 128 cols

    // prologue: stage 0 (kt = 0)
    {
        const __half* ap = Ag + (size_t)ar*Kk + ac;
        uint32_t ad = sA + (ar*APAD + ac)*2;
        cp16(ad, ap);
        cp16(ad + 64*APAD*2, ap + (size_t)64*Kk);
        const __half* bp = Wg + (size_t)bk*Nn + bn;
        uint32_t bd = sB + (bk*BPAD + bn)*2;
        cp16(bd, bp);
        cp16(bd + 16*BPAD*2, bp + (size_t)16*Nn);
        asm volatile("cp.async.commit_group;");
    }

    const int NKT = Kk / BKk;   // 32
    for (int kt = 0; kt < NKT; ++kt){
        const int st = kt & 1;
        if (kt + 1 < NKT){
            const int st2 = (kt+1)&1;
            const __half* ap = Ag + (size_t)ar*Kk + (kt+1)*BKk + ac;
            uint32_t ad = sA + st2*STAGE_A + (ar*APAD + ac)*2;
            cp16(ad, ap);
            cp16(ad + 64*APAD*2, ap + (size_t)64*Kk);
            const __half* bp = Wg + (size_t)((kt+1)*BKk + bk)*Nn + bn;
            uint32_t bd = sB + st2*STAGE_B + (bk*BPAD + bn)*2;
            cp16(bd, bp);
            cp16(bd + 16*BPAD*2, bp + (size_t)16*Nn);
            asm volatile("cp.async.commit_group;");
            asm volatile("cp.async.wait_group 1;");
        } else {
            asm volatile("cp.async.wait_group 0;");
        }
        __syncthreads();

        #pragma unroll
        for (int kk = 0; kk < 2; ++kk){
            uint32_t a[4][4];
            const int arow = wm*64 + (lane & 15);
            const int acol = kk*16 + (lane >> 4)*8;
            #pragma unroll
            for (int mt=0; mt<4; mt++){
                uint32_t ad = sA + st*STAGE_A + (((arow + mt*16)*APAD) + acol)*2;
                ldsm_x4(a[mt][0],a[mt][1],a[mt][2],a[mt][3], ad);
            }
            uint32_t bfr[4][2];
            const int brow = kk*16 + (lane & 15);
            #pragma unroll
            for (int np=0; np<2; np++){
                const int bcol = wn*32 + np*16 + (lane >> 4)*8;
                uint32_t bd = sB + st*STAGE_B + (brow*BPAD + bcol)*2;
                uint32_t r0,r1,r2,r3;
                ldsm_x4t(r0,r1,r2,r3, bd);
                bfr[2*np][0]=r0;   bfr[2*np][1]=r1;
                bfr[2*np+1][0]=r2; bfr[2*np+1][1]=r3;
            }
            #pragma unroll
            for (int mt=0; mt<4; mt++)
                #pragma unroll
                for (int nt=0; nt<4; nt++)
                    mma16816(acc[mt][nt], a[mt], bfr[nt]);
        }
        __syncthreads();
    }

    // epilogue: add hv, store fp32 (128-row M tiles never cross a batch boundary)
    const int bIdx = m0 >> 9;
    #pragma unroll
    for (int mt=0; mt<4; mt++){
        #pragma unroll
        for (int nt=0; nt<4; nt++){
            const int row = m0 + wm*64 + mt*16 + (lane >> 2);
            const int col = n0 + wn*32 + nt*8 + (lane & 3)*2;
            float2 hv2 = *(const float2*)&g_hv[bIdx*Nn + col];
            float2 o0 = make_float2(acc[mt][nt][0]+hv2.x, acc[mt][nt][1]+hv2.y);
            float2 o1 = make_float2(acc[mt][nt][2]+hv2.x, acc[mt][nt][3]+hv2.y);
            *(float2*)&g_G[(size_t)row*Nn + col]     = o0;
            *(float2*)&g_G[(size_t)(row+8)*Nn + col] = o1;
        }
    }
}

// ================= phase 2: activations + cumprod + transposed output =================
__device__ __forceinline__ float sigm(float x){
    return __fdividef(1.f, 1.f + __expf(-x));
}
__device__ __forceinline__ float tanh_f(float x){
    float ax = fabsf(x);
    float e = __expf(-2.f*ax);
    float t = __fdividef(1.f - e, 1.f + e);
    return copysignf(t, x);
}

#define TPAD 532
__global__ __launch_bounds__(256) void phase2_kernel(const float* __restrict__ c0,
                                                     float* __restrict__ out){
    __shared__ __align__(16) float tile[8][TPAD];   // [h_local][s_local*32 + b]
    const int hl = threadIdx.x & 7;
    const int b  = threadIdx.x >> 3;
    const int hblk = blockIdx.x * 8;
    const int h = hblk + hl;
    float c = c0[b*Hh + h];
    const float4* gp = ((const float4*)g_G) + (size_t)b*Ss*1024 + h;  // 4h gate quad
    float lastO = 0.f, lastR = 0.f;
    const int w = threadIdx.x >> 5, ln = threadIdx.x & 31;

    for (int sc = 0; sc < 32; ++sc){
        float4 gv[16];
        #pragma unroll
        for (int j=0;j<16;j++) gv[j] = gp[(size_t)(sc*16 + j)*1024];
        #pragma unroll
        for (int j=0;j<16;j++){
            float F  = sigm(gv[j].x);
            float I  = sigm(gv[j].y);
            float Nc = tanh_f(gv[j].z);
            float O  = sigm(gv[j].w);
            c *= F;
            float r = c + Nc*I;
            float o = tanh_f(r)*O;
            tile[hl][j*32 + b] = o;
            if (sc==31 && j==15){ lastO = o; lastR = r; }
        }
        __syncthreads();
        // warp w owns h_local = w: writes 512 contiguous floats of out_seq
        float4* dst = (float4*)(out + (size_t)(hblk + w)*16384 + sc*512);
        #pragma unroll
        for (int q=0;q<4;q++){
            float4 v = *(const float4*)&tile[w][(q*32+ln)*4];
            dst[q*32+ln] = v;
        }
        __syncthreads();
    }
    // out[:, -1, :] and r[:, -1, :]
    out[(size_t)16777216 + b*Hh + h]          = lastO;
    out[(size_t)16777216 + 32768 + b*Hh + h]  = lastR;
}

// ================= launch =================
extern "C" void kernel_launch(void* const* d_in, const int* in_sizes, int n_in,
                              void* d_out, int out_size) {
    (void)in_sizes; (void)n_in; (void)out_size;
    const float* inp = (const float*)d_in[0];
    const float* h0  = (const float*)d_in[1];
    const float* c0  = (const float*)d_in[2];
    const float* Uf  = (const float*)d_in[3];
    const float* Vf  = (const float*)d_in[4];
    const float* Bf  = (const float*)d_in[5];
    const float* Ui  = (const float*)d_in[6];
    const float* Vi  = (const float*)d_in[7];
    const float* Bi  = (const float*)d_in[8];
    const float* Ul  = (const float*)d_in[9];
    const float* Vl  = (const float*)d_in[10];
    const float* Bl  = (const float*)d_in[11];
    const float* Uu  = (const float*)d_in[12];
    const float* Vu  = (const float*)d_in[13];
    const float* Bu  = (const float*)d_in[14];
    float* out = (float*)d_out;

    conv_inp_kernel<<<(Mm*(size_t)Kk/4)/256, 256>>>(inp);
    pack_w_kernel<<<(Kk*Hh)/256, 256>>>(Uf, Ui, Ul, Uu);
    hv_kernel<<<Bb*4, 256>>>(h0, Vf, Vi, Vl, Vu, Bf, Bi, Bl, Bu);
    gemm_kernel<<<dim3(Nn/BN, Mm/BM), 256>>>();
    phase2_kernel<<<Hh/8, 256>>>(c0, out);
}

// round 3
// speedup vs baseline: 1.2885x; 1.2885x over previous
#include <cuda_runtime.h>
#include <cuda_fp16.h>
#include <cstdint>

#define Bb 32
#define Ss 512
#define Dd 1024
#define Hh 1024
#define Mm (Bb*Ss)     // 16384
#define Nn 4096        // 4 gates * H, interleaved n = 4*h + g  (g: 0=f,1=i,2=l,3=u)
#define Kk 1024

// ---- scratch (device globals; no allocation allowed) ----
__device__ __half g_A[(size_t)Mm*Kk];     // fp16 inp, row-major [m][k]
__device__ __half g_W[(size_t)Kk*Nn];     // fp16 packed weights [k][4h+g]
__device__ __half g_Gh[(size_t)Mm*Nn];    // gate pre-activations (fp16, hv added)
__device__ float  g_hv[Bb*Nn];            // h0@V_g + B_g, interleaved [b][4h+g]
__device__ float  g_hvp[8*32*4096];       // k-split partials [ks][b][g*1024+h]

// ================= convert / pack =================
__global__ void conv_inp_kernel(const float* __restrict__ inp){
    size_t i = (size_t)blockIdx.x*blockDim.x + threadIdx.x;   // float4 index
    float4 v = ((const float4*)inp)[i];
    __half2* dst = (__half2*)g_A + i*2;
    dst[0] = __floats2half2_rn(v.x, v.y);
    dst[1] = __floats2half2_rn(v.z, v.w);
}

__global__ void pack_w_kernel(const float* __restrict__ Uf, const float* __restrict__ Ui,
                              const float* __restrict__ Ul, const float* __restrict__ Uu){
    int idx = blockIdx.x*blockDim.x + threadIdx.x;  // k*1024 + h
    int k = idx >> 10, h = idx & 1023;
    __half2 p0 = __floats2half2_rn(Uf[idx], Ui[idx]);
    __half2 p1 = __floats2half2_rn(Ul[idx], Uu[idx]);
    __half2* dst = (__half2*)(g_W + (size_t)k*Nn + 4*h);
    dst[0] = p0; dst[1] = p1;
}

// ================= hv: k-split partial GEMV, reads each V exactly once =================
// grid 128: blockIdx.x = gh*8 + ks; gh = g*4 + hc
__global__ __launch_bounds__(256) void hv_part_kernel(const float* __restrict__ h0,
                          const float* __restrict__ Vf, const float* __restrict__ Vi,
                          const float* __restrict__ Vl, const float* __restrict__ Vu){
    const int ks = blockIdx.x & 7;
    const int gh = blockIdx.x >> 3;
    const int g  = gh >> 2, hc = gh & 3;
    const float* V = (g==0)?Vf:(g==1)?Vi:(g==2)?Vl:Vu;
    const int t = threadIdx.x;
    const int k0 = ks*128;
    __shared__ float s0[32][128];
    #pragma unroll
    for (int i = 0; i < 16; ++i){
        int idx = t + i*256;
        s0[idx >> 7][idx & 127] = h0[(idx >> 7)*1024 + k0 + (idx & 127)];
    }
    __syncthreads();
    const int h = hc*256 + t;
    float acc[32];
    #pragma unroll
    for (int b = 0; b < 32; ++b) acc[b] = 0.f;
    for (int k = 0; k < 128; ++k){
        float v = V[(size_t)(k0 + k)*1024 + h];
        #pragma unroll
        for (int b = 0; b < 32; ++b) acc[b] = fmaf(s0[b][k], v, acc[b]);
    }
    #pragma unroll
    for (int b = 0; b < 32; ++b)
        g_hvp[((size_t)ks*32 + b)*4096 + g*1024 + h] = acc[b];
}

__global__ __launch_bounds__(256) void hv_reduce_kernel(const float* __restrict__ Bf,
                          const float* __restrict__ Bi, const float* __restrict__ Bl,
                          const float* __restrict__ Bu){
    int idx = blockIdx.x*256 + threadIdx.x;   // 0..32767
    int b = idx >> 10, h = idx & 1023;
    float s0 = Bf[h], s1 = Bi[h], s2 = Bl[h], s3 = Bu[h];
    #pragma unroll
    for (int ks = 0; ks < 8; ++ks){
        const float* p = g_hvp + ((size_t)ks*32 + b)*4096;
        s0 += p[h]; s1 += p[1024 + h]; s2 += p[2048 + h]; s3 += p[3072 + h];
    }
    float4 o = make_float4(s0, s1, s2, s3);
    ((float4*)g_hv)[b*1024 + h] = o;
}

// ================= GEMM: Gh = A(fp16) * W(fp16) + hv, fp16 out =================
#define BM 128
#define BN 128
#define BKk 32
#define APAD 40
#define BPAD 136
#define ABYTES (BM*APAD*2)     // 10240
#define BBYTES (BKk*BPAD*2)    // 8704
#define NSTAGE 4
#define GEMM_SMEM (NSTAGE*(ABYTES+BBYTES))   // 75776

__device__ __forceinline__ void cp16(uint32_t d, const void* s){
    asm volatile("cp.async.cg.shared.global [%0], [%1], 16;" :: "r"(d), "l"(s));
}
#define CP_COMMIT() asm volatile("cp.async.commit_group;")
#define CP_WAIT(n)  asm volatile("cp.async.wait_group %0;" :: "n"(n))

__device__ __forceinline__ void ldsm_x4(uint32_t& r0,uint32_t& r1,uint32_t& r2,uint32_t& r3,uint32_t a){
    asm volatile("ldmatrix.sync.aligned.m8n8.x4.shared.b16 {%0,%1,%2,%3},[%4];"
        : "=r"(r0),"=r"(r1),"=r"(r2),"=r"(r3) : "r"(a));
}
__device__ __forceinline__ void ldsm_x4t(uint32_t& r0,uint32_t& r1,uint32_t& r2,uint32_t& r3,uint32_t a){
    asm volatile("ldmatrix.sync.aligned.m8n8.x4.trans.shared.b16 {%0,%1,%2,%3},[%4];"
        : "=r"(r0),"=r"(r1),"=r"(r2),"=r"(r3) : "r"(a));
}
__device__ __forceinline__ void mma16816(float* c, const uint32_t* a, const uint32_t* b){
    asm volatile("mma.sync.aligned.m16n8k16.row.col.f32.f16.f16.f32 "
        "{%0,%1,%2,%3},{%4,%5,%6,%7},{%8,%9},{%0,%1,%2,%3};"
        : "+f"(c[0]),"+f"(c[1]),"+f"(c[2]),"+f"(c[3])
        : "r"(a[0]),"r"(a[1]),"r"(a[2]),"r"(a[3]),"r"(b[0]),"r"(b[1]));
}
__device__ __forceinline__ uint32_t smem_u32(const void* p){
    uint32_t a;
    asm("{ .reg .u64 t; cvta.to.shared.u64 t, %1; cvt.u32.u64 %0, t; }" : "=r"(a) : "l"(p));
    return a;
}

__global__ __launch_bounds__(256,2) void gemm_kernel(){
    extern __shared__ __align__(16) char smem[];
    const uint32_t sA = smem_u32(smem);
    const uint32_t sB = sA + NSTAGE*ABYTES;
    const int tid = threadIdx.x;
    const int lane = tid & 31, warp = tid >> 5;
    const int wm = warp >> 2, wn = warp & 3;          // 2(m) x 4(n); warp tile 64x32
    const int m0 = blockIdx.y * BM, n0 = blockIdx.x * BN;

    float acc[4][4][4];
    #pragma unroll
    for (int i=0;i<4;i++)
        #pragma unroll
        for (int j=0;j<4;j++){ acc[i][j][0]=0.f; acc[i][j][1]=0.f; acc[i][j][2]=0.f; acc[i][j][3]=0.f; }

    const __half* Ag = g_A + (size_t)m0*Kk;
    const __half* Wg = g_W + n0;
    const int ar = tid >> 2, ac = (tid & 3)*8;        // A: 128 rows x 32 cols
    const int bk = tid >> 4, bn = (tid & 15)*8;       // B: 32 rows x 128 cols

    auto issue = [&](int st){
        const int buf = st & (NSTAGE-1);
        const __half* ap = Ag + (size_t)ar*Kk + st*BKk + ac;
        uint32_t ad = sA + buf*ABYTES + (ar*APAD + ac)*2;
        cp16(ad, ap);
        cp16(ad + 64*APAD*2, ap + (size_t)64*Kk);
        const __half* bp = Wg + (size_t)(st*BKk + bk)*Nn + bn;
        uint32_t bd = sB + buf*BBYTES + (bk*BPAD + bn)*2;
        cp16(bd, bp);
        cp16(bd + 16*BPAD*2, bp + (size_t)16*Nn);
    };

    auto compute = [&](int buf){
        #pragma unroll
        for (int kk = 0; kk < 2; ++kk){
            uint32_t a[4][4];
            const int arow = wm*64 + (lane & 15);
            const int acol = kk*16 + (lane >> 4)*8;
            #pragma unroll
            for (int mt=0; mt<4; mt++){
                uint32_t ad = sA + buf*ABYTES + (((arow + mt*16)*APAD) + acol)*2;
                ldsm_x4(a[mt][0],a[mt][1],a[mt][2],a[mt][3], ad);
            }
            uint32_t bfr[4][2];
            const int brow = kk*16 + (lane & 15);
            #pragma unroll
            for (int np=0; np<2; np++){
                const int bcol = wn*32 + np*16 + (lane >> 4)*8;
                uint32_t bd = sB + buf*BBYTES + (brow*BPAD + bcol)*2;
                uint32_t r0,r1,r2,r3;
                ldsm_x4t(r0,r1,r2,r3, bd);
                bfr[2*np][0]=r0;   bfr[2*np][1]=r1;
                bfr[2*np+1][0]=r2; bfr[2*np+1][1]=r3;
            }
            #pragma unroll
            for (int mt=0; mt<4; mt++)
                #pragma unroll
                for (int nt=0; nt<4; nt++)
                    mma16816(acc[mt][nt], a[mt], bfr[nt]);
        }
    };

    // prologue: stages 0..2
    #pragma unroll
    for (int s = 0; s < NSTAGE-1; ++s){ issue(s); CP_COMMIT(); }

    const int NKT = Kk / BKk;   // 32
    for (int kt = 0; kt < NKT-3; ++kt){
        CP_WAIT(2);
        __syncthreads();
        issue(kt+3); CP_COMMIT();
        compute(kt & (NSTAGE-1));
    }
    // tail: stages 29,30,31 already in flight
    CP_WAIT(2); __syncthreads(); compute((NKT-3) & (NSTAGE-1));
    CP_WAIT(1); __syncthreads(); compute((NKT-2) & (NSTAGE-1));
    CP_WAIT(0); __syncthreads(); compute((NKT-1) & (NSTAGE-1));

    // epilogue: add hv, store fp16
    const int bIdx = m0 >> 9;
    #pragma unroll
    for (int mt=0; mt<4; mt++){
        #pragma unroll
        for (int nt=0; nt<4; nt++){
            const int row = m0 + wm*64 + mt*16 + (lane >> 2);
            const int col = n0 + wn*32 + nt*8 + (lane & 3)*2;
            float2 hv2 = *(const float2*)&g_hv[bIdx*Nn + col];
            __half2 o0 = __floats2half2_rn(acc[mt][nt][0]+hv2.x, acc[mt][nt][1]+hv2.y);
            __half2 o1 = __floats2half2_rn(acc[mt][nt][2]+hv2.x, acc[mt][nt][3]+hv2.y);
            *(__half2*)&g_Gh[(size_t)row*Nn + col]     = o0;
            *(__half2*)&g_Gh[(size_t)(row+8)*Nn + col] = o1;
        }
    }
}

// ================= phase 2: activations + cumprod + transposed output =================
__device__ __forceinline__ float sigm(float x){
    return __fdividef(1.f, 1.f + __expf(-x));
}
__device__ __forceinline__ float tanh_f(float x){
    float ax = fabsf(x);
    float e = __expf(-2.f*ax);
    float t = __fdividef(1.f - e, 1.f + e);
    return copysignf(t, x);
}

#define ROWPAD 516
__global__ __launch_bounds__(256) void phase2_kernel(const float* __restrict__ c0,
                                                     float* __restrict__ out){
    __shared__ __align__(16) float tile[8][ROWPAD];   // [h_local][s_local*32 + b]
    const int t = threadIdx.x;
    const int q = t & 7;            // h_local
    const int b = t >> 3;
    const int hblk = blockIdx.x * 8;
    const int h = hblk + q;
    const int w = t >> 5, ln = t & 31;
    float c = c0[b*Hh + h];
    // gate quad for (m = b*512+s, h): 4 halves = uint2 at index m*1024 + h
    const uint2* gp = (const uint2*)g_Gh + (size_t)b*512*1024 + h;
    float lastO = 0.f, lastR = 0.f;

    for (int sc = 0; sc < 32; ++sc){
        uint2 gv[16];
        #pragma unroll
        for (int j=0;j<16;j++) gv[j] = gp[(size_t)(sc*16 + j)*1024];
        #pragma unroll
        for (int j=0;j<16;j++){
            float2 fi = __half22float2(*(const __half2*)&gv[j].x);
            float2 no = __half22float2(*(const __half2*)&gv[j].y);
            float F  = sigm(fi.x);
            float I  = sigm(fi.y);
            float Nc = tanh_f(no.x);
            float O  = sigm(no.y);
            c *= F;
            float r = c + Nc*I;
            float o = tanh_f(r)*O;
            tile[q][j*32 + b] = o;
            if (sc==31 && j==15){ lastO = o; lastR = r; }
        }
        __syncthreads();
        // warp w owns h_local = w: writes 512 contiguous floats of out_seq
        float4* dst = (float4*)(out + (size_t)(hblk + w)*16384 + sc*512);
        #pragma unroll
        for (int p=0;p<4;p++){
            float4 v = *(const float4*)&tile[w][(p*32+ln)*4];
            dst[p*32+ln] = v;
        }
        __syncthreads();
    }
    out[(size_t)16777216 + b*Hh + h]          = lastO;
    out[(size_t)16777216 + 32768 + b*Hh + h]  = lastR;
}

// ================= launch =================
extern "C" void kernel_launch(void* const* d_in, const int* in_sizes, int n_in,
                              void* d_out, int out_size) {
    (void)in_sizes; (void)n_in; (void)out_size;
    const float* inp = (const float*)d_in[0];
    const float* h0  = (const float*)d_in[1];
    const float* c0  = (const float*)d_in[2];
    const float* Uf  = (const float*)d_in[3];
    const float* Vf  = (const float*)d_in[4];
    const float* Bf  = (const float*)d_in[5];
    const float* Ui  = (const float*)d_in[6];
    const float* Vi  = (const float*)d_in[7];
    const float* Bi  = (const float*)d_in[8];
    const float* Ul  = (const float*)d_in[9];
    const float* Vl  = (const float*)d_in[10];
    const float* Bl  = (const float*)d_in[11];
    const float* Uu  = (const float*)d_in[12];
    const float* Vu  = (const float*)d_in[13];
    const float* Bu  = (const float*)d_in[14];
    float* out = (float*)d_out;

    cudaFuncSetAttribute(gemm_kernel,
                         cudaFuncAttributeMaxDynamicSharedMemorySize, GEMM_SMEM);

    conv_inp_kernel<<<(Mm*(size_t)Kk/4)/256, 256>>>(inp);
    pack_w_kernel<<<(Kk*Hh)/256, 256>>>(Uf, Ui, Ul, Uu);
    hv_part_kernel<<<128, 256>>>(h0, Vf, Vi, Vl, Vu);
    hv_reduce_kernel<<<128, 256>>>(Bf, Bi, Bl, Bu);
    gemm_kernel<<<dim3(Nn/BN, Mm/BM), 256, GEMM_SMEM>>>();
    phase2_kernel<<<Hh/8, 256>>>(c0, out);
}

// round 4
// speedup vs baseline: 1.2946x; 1.0048x over previous
#include <cuda_runtime.h>
#include <cuda_fp16.h>
#include <cstdint>

#define Bb 32
#define Ss 512
#define Dd 1024
#define Hh 1024
#define Mm (Bb*Ss)     // 16384, row order m' = s*32 + b
#define Nn 4096        // 4 gates * H, n = 4*h + g  (g: 0=f,1=i,2=l,3=u)
#define Kk 1024

// ---- scratch (device globals) ----
__device__ __half g_A[(size_t)Mm*Kk];     // fp16 inp, rows m' = s*32+b
__device__ __half g_W[(size_t)Kk*Nn];     // fp16 packed weights [k][4h+g]
__device__ __half g_Gt[(size_t)Mm*Nn];    // gates, layout ((h*512+s)*32+b)*4+g
__device__ float  g_hvT[1024*128];        // hvT[h][b*4+g]
__device__ float  g_hvp[8*32*4096];       // k-split partials [ks][b][g*1024+h]

// ================= convert / pack =================
__global__ void conv_inp_kernel(const float* __restrict__ inp){
    size_t i = (size_t)blockIdx.x*blockDim.x + threadIdx.x;   // float4 index
    int row = (int)(i >> 8);                 // 256 float4 per 1024-col row
    int cb  = (int)(i & 255);
    int b = row >> 9, s = row & 511;
    int nrow = s*32 + b;
    float4 v = ((const float4*)inp)[i];
    __half2* dst = (__half2*)(g_A + (size_t)nrow*1024 + cb*4);
    dst[0] = __floats2half2_rn(v.x, v.y);
    dst[1] = __floats2half2_rn(v.z, v.w);
}

__global__ void pack_w_kernel(const float* __restrict__ Uf, const float* __restrict__ Ui,
                              const float* __restrict__ Ul, const float* __restrict__ Uu){
    int idx = blockIdx.x*blockDim.x + threadIdx.x;  // k*1024 + h
    int k = idx >> 10, h = idx & 1023;
    __half2 p0 = __floats2half2_rn(Uf[idx], Ui[idx]);
    __half2 p1 = __floats2half2_rn(Ul[idx], Uu[idx]);
    __half2* dst = (__half2*)(g_W + (size_t)k*Nn + 4*h);
    dst[0] = p0; dst[1] = p1;
}

// ================= hv: k-split partial GEMV =================
__global__ __launch_bounds__(256) void hv_part_kernel(const float* __restrict__ h0,
                          const float* __restrict__ Vf, const float* __restrict__ Vi,
                          const float* __restrict__ Vl, const float* __restrict__ Vu){
    const int ks = blockIdx.x & 7;
    const int gh = blockIdx.x >> 3;
    const int g  = gh >> 2, hc = gh & 3;
    const float* V = (g==0)?Vf:(g==1)?Vi:(g==2)?Vl:Vu;
    const int t = threadIdx.x;
    const int k0 = ks*128;
    __shared__ float s0[32][128];
    #pragma unroll
    for (int i = 0; i < 16; ++i){
        int idx = t + i*256;
        s0[idx >> 7][idx & 127] = h0[(idx >> 7)*1024 + k0 + (idx & 127)];
    }
    __syncthreads();
    const int h = hc*256 + t;
    float acc[32];
    #pragma unroll
    for (int b = 0; b < 32; ++b) acc[b] = 0.f;
    for (int k = 0; k < 128; ++k){
        float v = V[(size_t)(k0 + k)*1024 + h];
        #pragma unroll
        for (int b = 0; b < 32; ++b) acc[b] = fmaf(s0[b][k], v, acc[b]);
    }
    #pragma unroll
    for (int b = 0; b < 32; ++b)
        g_hvp[((size_t)ks*32 + b)*4096 + g*1024 + h] = acc[b];
}

__global__ __launch_bounds__(256) void hv_reduce_kernel(const float* __restrict__ Bf,
                          const float* __restrict__ Bi, const float* __restrict__ Bl,
                          const float* __restrict__ Bu){
    int idx = blockIdx.x*256 + threadIdx.x;   // 0..32767
    int b = idx >> 10, h = idx & 1023;
    float s0 = Bf[h], s1 = Bi[h], s2 = Bl[h], s3 = Bu[h];
    #pragma unroll
    for (int ks = 0; ks < 8; ++ks){
        const float* p = g_hvp + ((size_t)ks*32 + b)*4096;
        s0 += p[h]; s1 += p[1024 + h]; s2 += p[2048 + h]; s3 += p[3072 + h];
    }
    ((float4*)g_hvT)[h*32 + b] = make_float4(s0, s1, s2, s3);
}

// ================= GEMM: fp16 mma.sync, BKk=64, 3 stages =================
#define BM 128
#define BN 128
#define BKk 64
#define APAD 72                 // halfs per A row
#define BPAD 136                // halfs per B row
#define ABYTES (BM*APAD*2)      // 18432
#define BBYTES (BKk*BPAD*2)     // 17408
#define NSTAGE 3
#define GEMM_SMEM (NSTAGE*(ABYTES+BBYTES))   // 107520
#define NPITCH 132              // epilogue fp32 tile pitch (floats)

__device__ __forceinline__ void cp16(uint32_t d, const void* s){
    asm volatile("cp.async.cg.shared.global [%0], [%1], 16;" :: "r"(d), "l"(s));
}
#define CP_COMMIT() asm volatile("cp.async.commit_group;")
#define CP_WAIT(n)  asm volatile("cp.async.wait_group %0;" :: "n"(n))

__device__ __forceinline__ void ldsm_x4(uint32_t& r0,uint32_t& r1,uint32_t& r2,uint32_t& r3,uint32_t a){
    asm volatile("ldmatrix.sync.aligned.m8n8.x4.shared.b16 {%0,%1,%2,%3},[%4];"
        : "=r"(r0),"=r"(r1),"=r"(r2),"=r"(r3) : "r"(a));
}
__device__ __forceinline__ void ldsm_x4t(uint32_t& r0,uint32_t& r1,uint32_t& r2,uint32_t& r3,uint32_t a){
    asm volatile("ldmatrix.sync.aligned.m8n8.x4.trans.shared.b16 {%0,%1,%2,%3},[%4];"
        : "=r"(r0),"=r"(r1),"=r"(r2),"=r"(r3) : "r"(a));
}
__device__ __forceinline__ void mma16816(float* c, const uint32_t* a, const uint32_t* b){
    asm volatile("mma.sync.aligned.m16n8k16.row.col.f32.f16.f16.f32 "
        "{%0,%1,%2,%3},{%4,%5,%6,%7},{%8,%9},{%0,%1,%2,%3};"
        : "+f"(c[0]),"+f"(c[1]),"+f"(c[2]),"+f"(c[3])
        : "r"(a[0]),"r"(a[1]),"r"(a[2]),"r"(a[3]),"r"(b[0]),"r"(b[1]));
}
__device__ __forceinline__ uint32_t smem_u32(const void* p){
    uint32_t a;
    asm("{ .reg .u64 t; cvta.to.shared.u64 t, %1; cvt.u32.u64 %0, t; }" : "=r"(a) : "l"(p));
    return a;
}

__global__ __launch_bounds__(256,2) void gemm_kernel(){
    extern __shared__ __align__(16) char smem[];
    const uint32_t sA = smem_u32(smem);
    const uint32_t sB = sA + NSTAGE*ABYTES;
    const int tid = threadIdx.x;
    const int lane = tid & 31, warp = tid >> 5;
    const int wm = warp >> 2, wn = warp & 3;          // 2(m) x 4(n); warp tile 64x32
    const int m0 = blockIdx.y * BM, n0 = blockIdx.x * BN;

    float acc[4][4][4];
    #pragma unroll
    for (int i=0;i<4;i++)
        #pragma unroll
        for (int j=0;j<4;j++){ acc[i][j][0]=0.f; acc[i][j][1]=0.f; acc[i][j][2]=0.f; acc[i][j][3]=0.f; }

    const __half* Ag = g_A + (size_t)m0*Kk;
    const __half* Wg = g_W + n0;

    auto issue = [&](int st, int buf){
        const int k0 = st*BKk;
        #pragma unroll
        for (int i = 0; i < 4; ++i){          // A: 128r x 64c, 1024 chunks
            int idx = tid + i*256;
            int row = idx >> 3, c = idx & 7;
            cp16(sA + buf*ABYTES + (row*APAD + c*8)*2,
                 Ag + (size_t)row*Kk + k0 + c*8);
        }
        #pragma unroll
        for (int i = 0; i < 4; ++i){          // B: 64r x 128c, 1024 chunks
            int idx = tid + i*256;
            int row = idx >> 4, c = idx & 15;
            cp16(sB + buf*BBYTES + (row*BPAD + c*8)*2,
                 Wg + (size_t)(k0 + row)*Nn + c*8);
        }
    };

    auto compute = [&](int buf){
        #pragma unroll
        for (int kk = 0; kk < 4; ++kk){
            uint32_t a[4][4];
            const int arow = wm*64 + (lane & 15);
            const int acol = kk*16 + (lane >> 4)*8;
            #pragma unroll
            for (int mt=0; mt<4; mt++){
                uint32_t ad = sA + buf*ABYTES + (((arow + mt*16)*APAD) + acol)*2;
                ldsm_x4(a[mt][0],a[mt][1],a[mt][2],a[mt][3], ad);
            }
            uint32_t bfr[4][2];
            const int brow = kk*16 + (lane & 15);
            #pragma unroll
            for (int np=0; np<2; np++){
                const int bcol = wn*32 + np*16 + (lane >> 4)*8;
                uint32_t bd = sB + buf*BBYTES + (brow*BPAD + bcol)*2;
                uint32_t r0,r1,r2,r3;
                ldsm_x4t(r0,r1,r2,r3, bd);
                bfr[2*np][0]=r0;   bfr[2*np][1]=r1;
                bfr[2*np+1][0]=r2; bfr[2*np+1][1]=r3;
            }
            #pragma unroll
            for (int mt=0; mt<4; mt++)
                #pragma unroll
                for (int nt=0; nt<4; nt++)
                    mma16816(acc[mt][nt], a[mt], bfr[nt]);
        }
    };

    issue(0,0); CP_COMMIT();
    issue(1,1); CP_COMMIT();

    const int NKT = Kk / BKk;   // 16
    int buf = 0;
    for (int kt = 0; kt < NKT-2; ++kt){
        CP_WAIT(1);
        __syncthreads();
        int wbuf = buf + 2; if (wbuf >= 3) wbuf -= 3;
        issue(kt+2, wbuf); CP_COMMIT();
        compute(buf);
        if (++buf == 3) buf = 0;
    }
    CP_WAIT(1); __syncthreads(); compute(buf); if (++buf == 3) buf = 0;
    CP_WAIT(0); __syncthreads(); compute(buf);

    // ---- epilogue: smem transpose -> g_Gt[h][s][b][g] fp16, + hvT ----
    __syncthreads();
    float* sT = (float*)smem;   // 128 x NPITCH
    #pragma unroll
    for (int mt=0; mt<4; mt++){
        #pragma unroll
        for (int nt=0; nt<4; nt++){
            const int row = wm*64 + mt*16 + (lane >> 2);
            const int col = wn*32 + nt*8 + (lane & 3)*2;
            *(float2*)&sT[row*NPITCH + col]     = make_float2(acc[mt][nt][0], acc[mt][nt][1]);
            *(float2*)&sT[(row+8)*NPITCH + col] = make_float2(acc[mt][nt][2], acc[mt][nt][3]);
        }
    }
    __syncthreads();

    const int hbase = n0 >> 2;        // 32 h per CTA
    const int s0 = m0 >> 5;           // 4 s per CTA (m' = s*32+b)
    const int sl = lane >> 3, c = lane & 7;
    #pragma unroll
    for (int hb = 0; hb < 4; ++hb){
        const int hl = hb*8 + warp;
        const int hglob = hbase + hl;
        const int s = s0 + sl;
        uint32_t pk[8];
        #pragma unroll
        for (int db = 0; db < 4; ++db){
            const int b = 4*c + db;
            float4 v  = *(const float4*)&sT[(sl*32 + b)*NPITCH + hl*4];
            float4 hv = ((const float4*)g_hvT)[hglob*32 + b];
            __half2 lo = __floats2half2_rn(v.x + hv.x, v.y + hv.y);
            __half2 hi = __floats2half2_rn(v.z + hv.z, v.w + hv.w);
            pk[db*2]   = *(uint32_t*)&lo;
            pk[db*2+1] = *(uint32_t*)&hi;
        }
        char* dst = (char*)g_Gt + ((size_t)(hglob*512 + s)*256) + c*32;
        *(uint4*)dst       = make_uint4(pk[0], pk[1], pk[2], pk[3]);
        *(uint4*)(dst+16)  = make_uint4(pk[4], pk[5], pk[6], pk[7]);
    }
}

// ================= phase 2: no smem, fully coalesced =================
__device__ __forceinline__ float sigm(float x){
    return __fdividef(1.f, 1.f + __expf(-x));
}
__device__ __forceinline__ float tanh_f(float x){
    float ax = fabsf(x);
    float e = __expf(-2.f*ax);
    float t = __fdividef(1.f - e, 1.f + e);
    return copysignf(t, x);
}

// grid 256, block 128: warp = one h, lanes = b
__global__ __launch_bounds__(128) void phase2_kernel(const float* __restrict__ c0,
                                                     float* __restrict__ out){
    const int t = threadIdx.x;
    const int w = t >> 5, b = t & 31;
    const int h = blockIdx.x*4 + w;
    float c = c0[b*Hh + h];
    const uint2* gp = (const uint2*)g_Gt + (size_t)h*512*32 + b;
    float* o = out + (size_t)h*16384 + b;
    float lastO = 0.f, lastR = 0.f;

    #pragma unroll 1
    for (int sc = 0; sc < 32; ++sc){
        uint2 gv[16];
        #pragma unroll
        for (int j = 0; j < 16; ++j) gv[j] = gp[(size_t)(sc*16 + j)*32];
        float ov[16];
        #pragma unroll
        for (int j = 0; j < 16; ++j){
            float2 fi = __half22float2(*(const __half2*)&gv[j].x);
            float2 no = __half22float2(*(const __half2*)&gv[j].y);
            float F  = sigm(fi.x);
            float I  = sigm(fi.y);
            float Nc = tanh_f(no.x);
            float O  = sigm(no.y);
            c *= F;
            float r = c + Nc*I;
            ov[j] = tanh_f(r)*O;
            if (sc == 31 && j == 15){ lastO = ov[j]; lastR = r; }
        }
        #pragma unroll
        for (int j = 0; j < 16; ++j) o[(size_t)(sc*16 + j)*32] = ov[j];
    }
    out[(size_t)16777216 + b*Hh + h]          = lastO;
    out[(size_t)16777216 + 32768 + b*Hh + h]  = lastR;
}

// ================= launch =================
extern "C" void kernel_launch(void* const* d_in, const int* in_sizes, int n_in,
                              void* d_out, int out_size) {
    (void)in_sizes; (void)n_in; (void)out_size;
    const float* inp = (const float*)d_in[0];
    const float* h0  = (const float*)d_in[1];
    const float* c0  = (const float*)d_in[2];
    const float* Uf  = (const float*)d_in[3];
    const float* Vf  = (const float*)d_in[4];
    const float* Bf  = (const float*)d_in[5];
    const float* Ui  = (const float*)d_in[6];
    const float* Vi  = (const float*)d_in[7];
    const float* Bi  = (const float*)d_in[8];
    const float* Ul  = (const float*)d_in[9];
    const float* Vl  = (const float*)d_in[10];
    const float* Bl  = (const float*)d_in[11];
    const float* Uu  = (const float*)d_in[12];
    const float* Vu  = (const float*)d_in[13];
    const float* Bu  = (const float*)d_in[14];
    float* out = (float*)d_out;

    cudaFuncSetAttribute(gemm_kernel,
                         cudaFuncAttributeMaxDynamicSharedMemorySize, GEMM_SMEM);

    conv_inp_kernel<<<(Mm*(size_t)Kk/4)/256, 256>>>(inp);
    pack_w_kernel<<<(Kk*Hh)/256, 256>>>(Uf, Ui, Ul, Uu);
    hv_part_kernel<<<128, 256>>>(h0, Vf, Vi, Vl, Vu);
    hv_reduce_kernel<<<128, 256>>>(Bf, Bi, Bl, Bu);
    gemm_kernel<<<dim3(Nn/BN, Mm/BM), 256, GEMM_SMEM>>>();
    phase2_kernel<<<256, 128>>>(c0, out);
}